// round 1
// baseline (speedup 1.0000x reference)
#include <cuda_runtime.h>
#include <math.h>

#define BB   2
#define TT   2048
#define DD   1024
#define NH   16
#define NKV  4
#define HD   64
#define KD   256
#define RANK 8
#define NTOK (BB*TT)
#define GQ   (NH/NKV)

// scratch (static device allocations — allowed)
__device__ float g_Wq[DD*DD];     // merged Wq + Bq@Aq
__device__ float g_Wv[KD*DD];     // merged Wv + Bv@Av
__device__ float g_q[NTOK*DD];
__device__ float g_k[NTOK*KD];
__device__ float g_v[NTOK*KD];
__device__ float g_y[NTOK*DD];

// ---------------------------------------------------------------------------
// W_eff[o,d] = W[o,d] + sum_r Bm[o,r]*Am[r,d]    (ALPHA = 1)
// ---------------------------------------------------------------------------
__global__ void merge_w(const float* __restrict__ W, const float* __restrict__ Am,
                        const float* __restrict__ Bm, float* __restrict__ out, int rows) {
    int idx = blockIdx.x * blockDim.x + threadIdx.x;
    if (idx >= rows * DD) return;
    int o = idx / DD, d = idx - o * DD;
    float acc = W[idx];
#pragma unroll
    for (int r = 0; r < RANK; r++) acc += Bm[o*RANK + r] * Am[r*DD + d];
    out[idx] = acc;
}

// ---------------------------------------------------------------------------
// C[M,N] = A[M,K] @ W[N,K]^T.  M,N multiples of 64; K multiple of 16.
// 256 threads, 64x64 tile, BK=16, 4x4 micro-tile per thread.
// ---------------------------------------------------------------------------
__global__ void sgemm_nt(const float* __restrict__ A, const float* __restrict__ W,
                         float* __restrict__ C, int M, int N, int K) {
    __shared__ float As[16][65];
    __shared__ float Ws[16][65];
    int tid = threadIdx.x;
    int tx = tid & 15, ty = tid >> 4;
    int m0 = blockIdx.y << 6, n0 = blockIdx.x << 6;
    int lrow = tid >> 2;            // 0..63
    int lcol = (tid & 3) << 2;      // 0,4,8,12
    float acc[4][4] = {};
    for (int k0 = 0; k0 < K; k0 += 16) {
        float4 a = *(const float4*)(A + (size_t)(m0 + lrow) * K + k0 + lcol);
        float4 w = *(const float4*)(W + (size_t)(n0 + lrow) * K + k0 + lcol);
        As[lcol+0][lrow]=a.x; As[lcol+1][lrow]=a.y; As[lcol+2][lrow]=a.z; As[lcol+3][lrow]=a.w;
        Ws[lcol+0][lrow]=w.x; Ws[lcol+1][lrow]=w.y; Ws[lcol+2][lrow]=w.z; Ws[lcol+3][lrow]=w.w;
        __syncthreads();
#pragma unroll
        for (int kk = 0; kk < 16; kk++) {
            float av[4], wv[4];
#pragma unroll
            for (int i = 0; i < 4; i++) av[i] = As[kk][(ty<<2)+i];
#pragma unroll
            for (int j = 0; j < 4; j++) wv[j] = Ws[kk][(tx<<2)+j];
#pragma unroll
            for (int i = 0; i < 4; i++)
#pragma unroll
                for (int j = 0; j < 4; j++) acc[i][j] += av[i]*wv[j];
        }
        __syncthreads();
    }
#pragma unroll
    for (int i = 0; i < 4; i++) {
        float4 o4 = make_float4(acc[i][0], acc[i][1], acc[i][2], acc[i][3]);
        *(float4*)(C + (size_t)(m0 + (ty<<2) + i) * N + n0 + (tx<<2)) = o4;
    }
}

// ---------------------------------------------------------------------------
// Per-head RMSNorm + partial RoPE (pd=16) + optional gain. One warp per head.
// buf layout: (tok, nheads, HD) contiguous. In-place.
// ---------------------------------------------------------------------------
__global__ void post_norm_rope(float* __restrict__ buf, const float* __restrict__ gain,
                               int nheads) {
    int head = blockIdx.x;                 // tok*nheads + h
    int h    = head % nheads;
    int tok  = head / nheads;
    int t    = tok % TT;
    int lane = threadIdx.x;                // 32 threads
    float* base = buf + (size_t)head * HD;
    float x0 = base[lane], x1 = base[lane + 32];
    float ss = x0*x0 + x1*x1;
#pragma unroll
    for (int off = 16; off; off >>= 1) ss += __shfl_xor_sync(0xffffffffu, ss, off);
    float rn = rsqrtf(ss * (1.0f/HD) + 1.1920929e-07f);
    x0 *= rn; x1 *= rn;
    // partial rope: dims 0..15 live in x0 of lanes 0..15. Pair (j, j+8).
    float xp = __shfl_xor_sync(0xffffffffu, x0, 8);
    if (lane < 16) {
        int j = lane & 7;
        float inv = powf(10000.0f, -(float)(2*j) * (1.0f/16.0f));
        float ang = (float)t * inv;
        float s, c;
        sincosf(ang, &s, &c);
        x0 = (lane < 8) ? (x0*c + xp*s)      // x1*cos + x2*sin
                        : (xp*s - x0*c);     // -x2*cos + x1*sin
    }
    float gg = gain ? gain[h] : 1.0f;
    base[lane]      = x0 * gg;
    base[lane + 32] = x1 * gg;
}

// ---------------------------------------------------------------------------
// Causal flash attention, fp32. grid (T/64, NH, B), 256 threads.
// 64 q rows per block, 64-wide K/V tiles, online softmax, GQA h->h/GQ.
// ---------------------------------------------------------------------------
__global__ void flash_attn() {
    extern __shared__ float sm[];
    float (*Qs)[65] = (float(*)[65])(sm);              // [d][row]
    float (*Ks)[65] = (float(*)[65])(sm + 64*65);      // [d][col]
    float (*Vs)[65] = (float(*)[65])(sm + 2*64*65);    // [col][d]
    float (*Ps)[65] = (float(*)[65])(sm + 3*64*65);    // [row][col]

    int q0 = blockIdx.x << 6;
    int h = blockIdx.y, b = blockIdx.z;
    int hkv = h / GQ;
    int tid = threadIdx.x;
    int tx = tid & 15, ty = tid >> 4;

    // load Q tile (transposed into smem)
#pragma unroll
    for (int it = 0; it < 4; it++) {
        int idx = tid + (it << 8);
        int row = idx >> 4;
        int d4 = (idx & 15) << 2;
        const float* src = g_q + ((size_t)((b*TT + q0 + row)*NH + h))*HD + d4;
        float4 v = *(const float4*)src;
        Qs[d4+0][row]=v.x; Qs[d4+1][row]=v.y; Qs[d4+2][row]=v.z; Qs[d4+3][row]=v.w;
    }

    float m[4], l[4], O[4][4];
#pragma unroll
    for (int i = 0; i < 4; i++) {
        m[i] = -1e30f; l[i] = 0.f;
#pragma unroll
        for (int j = 0; j < 4; j++) O[i][j] = 0.f;
    }

    int ktend = q0 >> 6;
    for (int kt = 0; kt <= ktend; kt++) {
        __syncthreads();
#pragma unroll
        for (int it = 0; it < 4; it++) {
            int idx = tid + (it << 8);
            int row = idx >> 4;
            int d4 = (idx & 15) << 2;
            size_t kbase = ((size_t)((b*TT + (kt<<6) + row)*NKV + hkv))*HD + d4;
            float4 kv = *(const float4*)(g_k + kbase);
            Ks[d4+0][row]=kv.x; Ks[d4+1][row]=kv.y; Ks[d4+2][row]=kv.z; Ks[d4+3][row]=kv.w;
            float4 vv = *(const float4*)(g_v + kbase);
            Vs[row][d4+0]=vv.x; Vs[row][d4+1]=vv.y; Vs[row][d4+2]=vv.z; Vs[row][d4+3]=vv.w;
        }
        __syncthreads();

        // S = Q @ K^T
        float s[4][4] = {};
#pragma unroll 8
        for (int d = 0; d < 64; d++) {
            float qv[4], kv[4];
#pragma unroll
            for (int i = 0; i < 4; i++) qv[i] = Qs[d][(ty<<2)+i];
#pragma unroll
            for (int j = 0; j < 4; j++) kv[j] = Ks[d][(tx<<2)+j];
#pragma unroll
            for (int i = 0; i < 4; i++)
#pragma unroll
                for (int j = 0; j < 4; j++) s[i][j] += qv[i]*kv[j];
        }
        const float SC = 0.125f;
        if (kt == ktend) {
#pragma unroll
            for (int i = 0; i < 4; i++)
#pragma unroll
                for (int j = 0; j < 4; j++)
                    s[i][j] = ((tx<<2)+j <= (ty<<2)+i) ? s[i][j]*SC : -1e30f;
        } else {
#pragma unroll
            for (int i = 0; i < 4; i++)
#pragma unroll
                for (int j = 0; j < 4; j++) s[i][j] *= SC;
        }

        // online softmax update
        float mnew[4], corr[4];
#pragma unroll
        for (int i = 0; i < 4; i++) {
            float rm = fmaxf(fmaxf(s[i][0], s[i][1]), fmaxf(s[i][2], s[i][3]));
#pragma unroll
            for (int off = 8; off; off >>= 1)
                rm = fmaxf(rm, __shfl_xor_sync(0xffffffffu, rm, off));
            mnew[i] = fmaxf(m[i], rm);
            corr[i] = __expf(m[i] - mnew[i]);
            m[i] = mnew[i];
        }
#pragma unroll
        for (int i = 0; i < 4; i++) {
            float sum = 0.f;
#pragma unroll
            for (int j = 0; j < 4; j++) { s[i][j] = __expf(s[i][j] - mnew[i]); sum += s[i][j]; }
#pragma unroll
            for (int off = 8; off; off >>= 1)
                sum += __shfl_xor_sync(0xffffffffu, sum, off);
            l[i] = l[i]*corr[i] + sum;
#pragma unroll
            for (int j = 0; j < 4; j++) O[i][j] *= corr[i];
        }
        // stage P
#pragma unroll
        for (int i = 0; i < 4; i++)
#pragma unroll
            for (int j = 0; j < 4; j++) Ps[(ty<<2)+i][(tx<<2)+j] = s[i][j];
        __syncthreads();
        // O += P @ V
#pragma unroll 8
        for (int c = 0; c < 64; c++) {
            float pv[4], vv[4];
#pragma unroll
            for (int i = 0; i < 4; i++) pv[i] = Ps[(ty<<2)+i][c];
#pragma unroll
            for (int j = 0; j < 4; j++) vv[j] = Vs[c][(tx<<2)+j];
#pragma unroll
            for (int i = 0; i < 4; i++)
#pragma unroll
                for (int j = 0; j < 4; j++) O[i][j] += pv[i]*vv[j];
        }
    }
#pragma unroll
    for (int i = 0; i < 4; i++) {
        float inv_l = 1.0f / l[i];
        size_t tok = (size_t)(b*TT + q0 + (ty<<2) + i);
#pragma unroll
        for (int j = 0; j < 4; j++)
            g_y[tok*DD + h*HD + (tx<<2) + j] = O[i][j] * inv_l;
    }
}

// ---------------------------------------------------------------------------
extern "C" void kernel_launch(void* const* d_in, const int* in_sizes, int n_in,
                              void* d_out, int out_size) {
    const float* x     = (const float*)d_in[0];
    const float* Wq    = (const float*)d_in[1];
    const float* Wk    = (const float*)d_in[2];
    const float* Wv    = (const float*)d_in[3];
    const float* Wproj = (const float*)d_in[4];
    const float* qgain = (const float*)d_in[5];
    const float* Aq    = (const float*)d_in[6];
    const float* Bq    = (const float*)d_in[7];
    const float* Av    = (const float*)d_in[8];
    const float* Bv    = (const float*)d_in[9];
    float* out = (float*)d_out;

    float *pWq, *pWv, *pq, *pk, *pv, *py;
    cudaGetSymbolAddress((void**)&pWq, g_Wq);
    cudaGetSymbolAddress((void**)&pWv, g_Wv);
    cudaGetSymbolAddress((void**)&pq,  g_q);
    cudaGetSymbolAddress((void**)&pk,  g_k);
    cudaGetSymbolAddress((void**)&pv,  g_v);
    cudaGetSymbolAddress((void**)&py,  g_y);

    // fold LoRA into weights
    merge_w<<<(DD*DD + 255)/256, 256>>>(Wq, Aq, Bq, pWq, DD);
    merge_w<<<(KD*DD + 255)/256, 256>>>(Wv, Av, Bv, pWv, KD);

    // projections
    sgemm_nt<<<dim3(DD/64, NTOK/64), 256>>>(x, pWq, pq, NTOK, DD, DD);
    sgemm_nt<<<dim3(KD/64, NTOK/64), 256>>>(x, Wk,  pk, NTOK, KD, DD);
    sgemm_nt<<<dim3(KD/64, NTOK/64), 256>>>(x, pWv, pv, NTOK, KD, DD);

    // rmsnorm + rope (+gain for q); v needs no post-processing
    post_norm_rope<<<NTOK*NH,  32>>>(pq, qgain, NH);
    post_norm_rope<<<NTOK*NKV, 32>>>(pk, nullptr, NKV);

    // attention
    int smem = 4 * 64 * 65 * (int)sizeof(float);
    cudaFuncSetAttribute(flash_attn, cudaFuncAttributeMaxDynamicSharedMemorySize, smem);
    flash_attn<<<dim3(TT/64, NH, BB), 256, smem>>>();

    // output projection
    sgemm_nt<<<dim3(DD/64, NTOK/64), 256>>>(py, Wproj, out, NTOK, DD, DD);
}

// round 7
// speedup vs baseline: 1.0629x; 1.0629x over previous
#include <cuda_runtime.h>
#include <math.h>
#include <stdint.h>

#define BB   2
#define TT   2048
#define DD   1024
#define NH   16
#define NKV  4
#define HD   64
#define KD   256
#define RANK 8
#define NTOK (BB*TT)
#define GQ   (NH/NKV)

// scratch (static device allocations — allowed)
__device__ float g_Wq[DD*DD];     // merged Wq + Bq@Aq
__device__ float g_Wv[KD*DD];     // merged Wv + Bv@Av
__device__ float g_q[NTOK*DD];
__device__ float g_k[NTOK*KD];
__device__ float g_v[NTOK*KD];
__device__ float g_y[NTOK*DD];

// ---------------------------------------------------------------------------
// W_eff[o,d] = W[o,d] + sum_r Bm[o,r]*Am[r,d]    (ALPHA = 1)
// ---------------------------------------------------------------------------
__global__ void merge_w(const float* __restrict__ W, const float* __restrict__ Am,
                        const float* __restrict__ Bm, float* __restrict__ out, int rows) {
    int idx = blockIdx.x * blockDim.x + threadIdx.x;
    if (idx >= rows * DD) return;
    int o = idx / DD, d = idx - o * DD;
    float acc = W[idx];
#pragma unroll
    for (int r = 0; r < RANK; r++) acc += Bm[o*RANK + r] * Am[r*DD + d];
    out[idx] = acc;
}

// ---------------------------------------------------------------------------
// C[M,N] = A[M,K] @ W[N,K]^T.  (round-1 proven SIMT GEMM)
// ---------------------------------------------------------------------------
__global__ void sgemm_nt(const float* __restrict__ A, const float* __restrict__ W,
                         float* __restrict__ C, int M, int N, int K) {
    __shared__ float As[16][65];
    __shared__ float Ws[16][65];
    int tid = threadIdx.x;
    int tx = tid & 15, ty = tid >> 4;
    int m0 = blockIdx.y << 6, n0 = blockIdx.x << 6;
    int lrow = tid >> 2;
    int lcol = (tid & 3) << 2;
    float acc[4][4] = {};
    for (int k0 = 0; k0 < K; k0 += 16) {
        float4 a = *(const float4*)(A + (size_t)(m0 + lrow) * K + k0 + lcol);
        float4 w = *(const float4*)(W + (size_t)(n0 + lrow) * K + k0 + lcol);
        As[lcol+0][lrow]=a.x; As[lcol+1][lrow]=a.y; As[lcol+2][lrow]=a.z; As[lcol+3][lrow]=a.w;
        Ws[lcol+0][lrow]=w.x; Ws[lcol+1][lrow]=w.y; Ws[lcol+2][lrow]=w.z; Ws[lcol+3][lrow]=w.w;
        __syncthreads();
#pragma unroll
        for (int kk = 0; kk < 16; kk++) {
            float av[4], wv[4];
#pragma unroll
            for (int i = 0; i < 4; i++) av[i] = As[kk][(ty<<2)+i];
#pragma unroll
            for (int j = 0; j < 4; j++) wv[j] = Ws[kk][(tx<<2)+j];
#pragma unroll
            for (int i = 0; i < 4; i++)
#pragma unroll
                for (int j = 0; j < 4; j++) acc[i][j] += av[i]*wv[j];
        }
        __syncthreads();
    }
#pragma unroll
    for (int i = 0; i < 4; i++) {
        float4 o4 = make_float4(acc[i][0], acc[i][1], acc[i][2], acc[i][3]);
        *(float4*)(C + (size_t)(m0 + (ty<<2) + i) * N + n0 + (tx<<2)) = o4;
    }
}

// ---------------------------------------------------------------------------
// Per-head RMSNorm + partial RoPE (pd=16) + optional gain. One warp per head.
// ---------------------------------------------------------------------------
__global__ void post_norm_rope(float* __restrict__ buf, const float* __restrict__ gain,
                               int nheads) {
    int head = blockIdx.x;
    int h    = head % nheads;
    int tok  = head / nheads;
    int t    = tok % TT;
    int lane = threadIdx.x;
    float* base = buf + (size_t)head * HD;
    float x0 = base[lane], x1 = base[lane + 32];
    float ss = x0*x0 + x1*x1;
#pragma unroll
    for (int off = 16; off; off >>= 1) ss += __shfl_xor_sync(0xffffffffu, ss, off);
    float rn = rsqrtf(ss * (1.0f/HD) + 1.1920929e-07f);
    x0 *= rn; x1 *= rn;
    float xp = __shfl_xor_sync(0xffffffffu, x0, 8);
    if (lane < 16) {
        int j = lane & 7;
        float inv = powf(10000.0f, -(float)(2*j) * (1.0f/16.0f));
        float ang = (float)t * inv;
        float s, c;
        sincosf(ang, &s, &c);
        x0 = (lane < 8) ? (x0*c + xp*s) : (xp*s - x0*c);
    }
    float gg = gain ? gain[h] : 1.0f;
    base[lane]      = x0 * gg;
    base[lane + 32] = x1 * gg;
}

// ---------------------------------------------------------------------------
// Flash attention v3: 128 q-rows x 128 k-cols tiles, 256 threads, fp32 SIMT.
// QK microtile 8x8 (S tile is 128 wide). PV/O microtile 8x4 (HD = 64 wide).
// grid (T/128, NH, B).
// ---------------------------------------------------------------------------
__global__ __launch_bounds__(256, 1) void flash3() {
    extern __shared__ __align__(16) float fsm[];
    float (*Qs)[132] = (float(*)[132])fsm;            // [d][row]   64x132
    float (*Ks)[132] = (float(*)[132])(fsm + 8448);   // [d][col]   64x132
    float (*Vs)[68]  = (float(*)[68]) (fsm + 16896);  // [col][d]  128x68
    float (*Ps)[132] = (float(*)[132])(fsm + 25600);  // [row][col]128x132

    int qt = blockIdx.x, h = blockIdx.y, b = blockIdx.z;
    int hkv = h / GQ;
    int tid = threadIdx.x;
    int tx = tid & 15, ty = tid >> 4;
    int q0 = qt << 7;

    for (int u = tid; u < 2048; u += 256) {
        int row = u >> 4, d4 = (u & 15) << 2;
        float4 v = *(const float4*)(g_q + ((size_t)((b*TT + q0 + row)*NH + h))*HD + d4);
        Qs[d4+0][row]=v.x; Qs[d4+1][row]=v.y; Qs[d4+2][row]=v.z; Qs[d4+3][row]=v.w;
    }

    float m[8], l[8], O[8][4];
#pragma unroll
    for (int i = 0; i < 8; i++) {
        m[i] = -1e30f; l[i] = 0.f;
#pragma unroll
        for (int j = 0; j < 4; j++) O[i][j] = 0.f;
    }

    for (int kt = 0; kt <= qt; kt++) {
        __syncthreads();
        for (int u = tid; u < 2048; u += 256) {
            int row = u >> 4, d4 = (u & 15) << 2;
            size_t base = ((size_t)((b*TT + (kt<<7) + row)*NKV + hkv))*HD + d4;
            float4 kv = *(const float4*)(g_k + base);
            Ks[d4+0][row]=kv.x; Ks[d4+1][row]=kv.y; Ks[d4+2][row]=kv.z; Ks[d4+3][row]=kv.w;
            float4 vv = *(const float4*)(g_v + base);
            *(float4*)&Vs[row][d4] = vv;
        }
        __syncthreads();

        // ---- S = Q @ K^T  (8x8 microtile over 128x128 S tile) ----
        float s8[8][8];
#pragma unroll
        for (int i = 0; i < 8; i++)
#pragma unroll
            for (int j = 0; j < 8; j++) s8[i][j] = 0.f;

#pragma unroll 2
        for (int d = 0; d < 64; d++) {
            float4 qa = *(float4*)&Qs[d][ty<<3], qb = *(float4*)&Qs[d][(ty<<3)+4];
            float4 ka = *(float4*)&Ks[d][tx<<3], kb = *(float4*)&Ks[d][(tx<<3)+4];
            float qv[8] = {qa.x,qa.y,qa.z,qa.w,qb.x,qb.y,qb.z,qb.w};
            float kv[8] = {ka.x,ka.y,ka.z,ka.w,kb.x,kb.y,kb.z,kb.w};
#pragma unroll
            for (int i = 0; i < 8; i++)
#pragma unroll
                for (int j = 0; j < 8; j++) s8[i][j] += qv[i]*kv[j];
        }

        const float SC = 0.125f;
        if (kt == qt) {
#pragma unroll
            for (int i = 0; i < 8; i++)
#pragma unroll
                for (int j = 0; j < 8; j++)
                    s8[i][j] = ((tx<<3)+j <= (ty<<3)+i) ? s8[i][j]*SC : -1e30f;
        } else {
#pragma unroll
            for (int i = 0; i < 8; i++)
#pragma unroll
                for (int j = 0; j < 8; j++) s8[i][j] *= SC;
        }

        // ---- online softmax (row state per ty-group row) ----
#pragma unroll
        for (int i = 0; i < 8; i++) {
            float rm = s8[i][0];
#pragma unroll
            for (int j = 1; j < 8; j++) rm = fmaxf(rm, s8[i][j]);
#pragma unroll
            for (int off = 8; off; off >>= 1)
                rm = fmaxf(rm, __shfl_xor_sync(0xffffffffu, rm, off));
            float mn = fmaxf(m[i], rm);
            float corr = __expf(m[i] - mn);
            m[i] = mn;
            float sum = 0.f;
#pragma unroll
            for (int j = 0; j < 8; j++) { s8[i][j] = __expf(s8[i][j] - mn); sum += s8[i][j]; }
#pragma unroll
            for (int off = 8; off; off >>= 1)
                sum += __shfl_xor_sync(0xffffffffu, sum, off);
            l[i] = l[i]*corr + sum;
#pragma unroll
            for (int j = 0; j < 4; j++) O[i][j] *= corr;
            *(float4*)&Ps[(ty<<3)+i][tx<<3]     = make_float4(s8[i][0], s8[i][1], s8[i][2], s8[i][3]);
            *(float4*)&Ps[(ty<<3)+i][(tx<<3)+4] = make_float4(s8[i][4], s8[i][5], s8[i][6], s8[i][7]);
        }
        __syncthreads();

        // ---- O += P @ V  (8x4 microtile: rows ty*8+i, cols tx*4+j, HD=64) ----
#pragma unroll 4
        for (int c = 0; c < 128; c++) {
            float4 va = *(float4*)&Vs[c][tx<<2];
            float vv[4] = {va.x, va.y, va.z, va.w};
#pragma unroll
            for (int i = 0; i < 8; i++) {
                float pv = Ps[(ty<<3)+i][c];
#pragma unroll
                for (int j = 0; j < 4; j++) O[i][j] += pv*vv[j];
            }
        }
    }

#pragma unroll
    for (int i = 0; i < 8; i++) {
        float inv = 1.0f / l[i];
        int row = q0 + (ty<<3) + i;
        float* dst = g_y + ((size_t)(b*TT + row))*DD + h*HD + (tx<<2);
        float4 o4 = make_float4(O[i][0]*inv, O[i][1]*inv, O[i][2]*inv, O[i][3]*inv);
        *(float4*)dst = o4;
    }
}

// ---------------------------------------------------------------------------
extern "C" void kernel_launch(void* const* d_in, const int* in_sizes, int n_in,
                              void* d_out, int out_size) {
    const float* x     = (const float*)d_in[0];
    const float* Wq    = (const float*)d_in[1];
    const float* Wk    = (const float*)d_in[2];
    const float* Wv    = (const float*)d_in[3];
    const float* Wproj = (const float*)d_in[4];
    const float* qgain = (const float*)d_in[5];
    const float* Aq    = (const float*)d_in[6];
    const float* Bq    = (const float*)d_in[7];
    const float* Av    = (const float*)d_in[8];
    const float* Bv    = (const float*)d_in[9];
    float* out = (float*)d_out;

    float *pWq, *pWv, *pq, *pk, *pv, *py;
    cudaGetSymbolAddress((void**)&pWq, g_Wq);
    cudaGetSymbolAddress((void**)&pWv, g_Wv);
    cudaGetSymbolAddress((void**)&pq,  g_q);
    cudaGetSymbolAddress((void**)&pk,  g_k);
    cudaGetSymbolAddress((void**)&pv,  g_v);
    cudaGetSymbolAddress((void**)&py,  g_y);

    // fold LoRA into weights
    merge_w<<<(DD*DD + 255)/256, 256>>>(Wq, Aq, Bq, pWq, DD);
    merge_w<<<(KD*DD + 255)/256, 256>>>(Wv, Av, Bv, pWv, KD);

    // projections (proven SIMT GEMM)
    sgemm_nt<<<dim3(DD/64, NTOK/64), 256>>>(x, pWq, pq, NTOK, DD, DD);
    sgemm_nt<<<dim3(KD/64, NTOK/64), 256>>>(x, Wk,  pk, NTOK, KD, DD);
    sgemm_nt<<<dim3(KD/64, NTOK/64), 256>>>(x, pWv, pv, NTOK, KD, DD);

    // rmsnorm + rope (+gain for q)
    post_norm_rope<<<NTOK*NH,  32>>>(pq, qgain, NH);
    post_norm_rope<<<NTOK*NKV, 32>>>(pk, nullptr, NKV);

    // attention (fixed: PV/O microtile is 8x4 over HD=64)
    int fsmB = 42496 * (int)sizeof(float);
    cudaFuncSetAttribute(flash3, cudaFuncAttributeMaxDynamicSharedMemorySize, fsmB);
    flash3<<<dim3(TT/128, NH, BB), 256, fsmB>>>();

    // output projection
    sgemm_nt<<<dim3(DD/64, NTOK/64), 256>>>(py, Wproj, out, NTOK, DD, DD);
}

// round 11
// speedup vs baseline: 1.3755x; 1.2941x over previous
#include <cuda_runtime.h>
#include <math.h>
#include <stdint.h>

#define BB   2
#define TT   2048
#define DD   1024
#define NH   16
#define NKV  4
#define HD   64
#define KD   256
#define RANK 8
#define NTOK (BB*TT)
#define GQ   (NH/NKV)

// scratch (static device allocations — allowed)
__device__ float g_Wq[DD*DD];     // merged Wq + Bq@Aq
__device__ float g_Wv[KD*DD];     // merged Wv + Bv@Av
__device__ float g_q[NTOK*DD];
__device__ float g_k[NTOK*KD];
__device__ float g_v[NTOK*KD];
__device__ float g_y[NTOK*DD];

// ---------------- helpers ---------------------------------------------------
__device__ __forceinline__ float to_tf32(float x) {
    uint32_t u; asm("cvt.rna.tf32.f32 %0, %1;" : "=r"(u) : "f"(x));
    return __uint_as_float(u);
}

// tf32 m16n8k8 mma.sync
__device__ __forceinline__ void mma_tf32(float& c0, float& c1, float& c2, float& c3,
                                         uint32_t a0, uint32_t a1, uint32_t a2, uint32_t a3,
                                         uint32_t b0, uint32_t b1) {
    asm volatile(
        "mma.sync.aligned.m16n8k8.row.col.f32.tf32.tf32.f32 "
        "{%0,%1,%2,%3}, {%4,%5,%6,%7}, {%8,%9}, {%0,%1,%2,%3};"
        : "+f"(c0), "+f"(c1), "+f"(c2), "+f"(c3)
        : "r"(a0), "r"(a1), "r"(a2), "r"(a3), "r"(b0), "r"(b1));
}

// ---------------------------------------------------------------------------
// W_eff[o,d] = W[o,d] + sum_r Bm[o,r]*Am[r,d]    (ALPHA = 1)
// ---------------------------------------------------------------------------
__global__ void merge_w(const float* __restrict__ W, const float* __restrict__ Am,
                        const float* __restrict__ Bm, float* __restrict__ out, int rows) {
    int idx = blockIdx.x * blockDim.x + threadIdx.x;
    if (idx >= rows * DD) return;
    int o = idx / DD, d = idx - o * DD;
    float acc = W[idx];
#pragma unroll
    for (int r = 0; r < RANK; r++) acc += Bm[o*RANK + r] * Am[r*DD + d];
    out[idx] = acc;
}

// ---------------------------------------------------------------------------
// tf32x3 split-precision tensor GEMM: C = A @ W^T, ~fp32 accuracy.
// a = hi + lo (Dekker split into two tf32); acc += hi*hi + hi*lo + lo*hi.
// 128x128 CTA tile, BK=32, register prefetch, 8 warps x (64x32) m16n8k8.
// Dynamic smem: hi/lo tiles for A and B, rows padded to 36 floats (73.7 KB).
// ---------------------------------------------------------------------------
__global__ __launch_bounds__(256, 1)
void gemm_mma3(const float* __restrict__ A, const float* __restrict__ W,
               float* __restrict__ C, int M, int N, int K) {
    extern __shared__ __align__(16) float sgm[];
    float* sa_hi = sgm;                 // 4608 floats each
    float* sa_lo = sgm + 4608;
    float* sb_hi = sgm + 9216;
    float* sb_lo = sgm + 13824;

    int tid = threadIdx.x;
    int wid = tid >> 5, lane = tid & 31;
    int g = lane >> 2, tg = lane & 3;       // fragment row group / k group
    int wm = wid >> 2, wn = wid & 3;        // warp tile: rows wm*64, cols wn*32
    int m0 = blockIdx.y << 7, n0 = blockIdx.x << 7;

    const float* aptr = A + (size_t)m0 * K;
    const float* bptr = W + (size_t)n0 * K;

    float acc[4][4][4];
#pragma unroll
    for (int mt = 0; mt < 4; mt++)
#pragma unroll
        for (int nt = 0; nt < 4; nt++)
#pragma unroll
            for (int r = 0; r < 4; r++) acc[mt][nt][r] = 0.f;

    int nk = K >> 5;
    float4 pa[4], pb[4];
#pragma unroll
    for (int it = 0; it < 4; it++) {
        int c = it * 256 + tid, r = c >> 3, c4 = (c & 7) << 2;
        pa[it] = *(const float4*)(aptr + (size_t)r * K + c4);
        pb[it] = *(const float4*)(bptr + (size_t)r * K + c4);
    }

    for (int k0 = 0; k0 < nk; k0++) {
        // split + store current chunk
#pragma unroll
        for (int it = 0; it < 4; it++) {
            int c = it * 256 + tid, r = c >> 3, c4 = (c & 7) << 2;
            float av[4] = {pa[it].x, pa[it].y, pa[it].z, pa[it].w};
            float bv[4] = {pb[it].x, pb[it].y, pb[it].z, pb[it].w};
            int off = r * 36 + c4;
#pragma unroll
            for (int e = 0; e < 4; e++) {
                float ah = to_tf32(av[e]);
                sa_hi[off + e] = ah;
                sa_lo[off + e] = to_tf32(av[e] - ah);
                float bh = to_tf32(bv[e]);
                sb_hi[off + e] = bh;
                sb_lo[off + e] = to_tf32(bv[e] - bh);
            }
        }
        __syncthreads();
        if (k0 + 1 < nk) {
            int koff = (k0 + 1) * 32;
#pragma unroll
            for (int it = 0; it < 4; it++) {
                int c = it * 256 + tid, r = c >> 3, c4 = (c & 7) << 2;
                pa[it] = *(const float4*)(aptr + (size_t)r * K + koff + c4);
                pb[it] = *(const float4*)(bptr + (size_t)r * K + koff + c4);
            }
        }
#pragma unroll
        for (int kk = 0; kk < 4; kk++) {
            uint32_t ah[4][4], al[4][4], bh[4][2], bl[4][2];
#pragma unroll
            for (int mt = 0; mt < 4; mt++) {
                int off = (wm * 64 + mt * 16 + g) * 36 + kk * 8 + tg;
                ah[mt][0] = __float_as_uint(sa_hi[off]);
                ah[mt][1] = __float_as_uint(sa_hi[off + 8 * 36]);
                ah[mt][2] = __float_as_uint(sa_hi[off + 4]);
                ah[mt][3] = __float_as_uint(sa_hi[off + 8 * 36 + 4]);
                al[mt][0] = __float_as_uint(sa_lo[off]);
                al[mt][1] = __float_as_uint(sa_lo[off + 8 * 36]);
                al[mt][2] = __float_as_uint(sa_lo[off + 4]);
                al[mt][3] = __float_as_uint(sa_lo[off + 8 * 36 + 4]);
            }
#pragma unroll
            for (int nt = 0; nt < 4; nt++) {
                int off = (wn * 32 + nt * 8 + g) * 36 + kk * 8 + tg;
                bh[nt][0] = __float_as_uint(sb_hi[off]);
                bh[nt][1] = __float_as_uint(sb_hi[off + 4]);
                bl[nt][0] = __float_as_uint(sb_lo[off]);
                bl[nt][1] = __float_as_uint(sb_lo[off + 4]);
            }
#pragma unroll
            for (int mt = 0; mt < 4; mt++)
#pragma unroll
                for (int nt = 0; nt < 4; nt++) {
                    // lo terms first (small), hi*hi last
                    mma_tf32(acc[mt][nt][0], acc[mt][nt][1], acc[mt][nt][2], acc[mt][nt][3],
                             al[mt][0], al[mt][1], al[mt][2], al[mt][3],
                             bh[nt][0], bh[nt][1]);
                    mma_tf32(acc[mt][nt][0], acc[mt][nt][1], acc[mt][nt][2], acc[mt][nt][3],
                             ah[mt][0], ah[mt][1], ah[mt][2], ah[mt][3],
                             bl[nt][0], bl[nt][1]);
                    mma_tf32(acc[mt][nt][0], acc[mt][nt][1], acc[mt][nt][2], acc[mt][nt][3],
                             ah[mt][0], ah[mt][1], ah[mt][2], ah[mt][3],
                             bh[nt][0], bh[nt][1]);
                }
        }
        __syncthreads();
    }

#pragma unroll
    for (int mt = 0; mt < 4; mt++) {
        int row = m0 + wm * 64 + mt * 16 + g;
#pragma unroll
        for (int nt = 0; nt < 4; nt++) {
            int col = n0 + wn * 32 + nt * 8 + tg * 2;
            *(float2*)(C + (size_t)row * N + col)       = make_float2(acc[mt][nt][0], acc[mt][nt][1]);
            *(float2*)(C + (size_t)(row + 8) * N + col) = make_float2(acc[mt][nt][2], acc[mt][nt][3]);
        }
    }
}

// ---------------------------------------------------------------------------
// Per-head RMSNorm + partial RoPE (pd=16) + optional gain. One warp per head.
// ---------------------------------------------------------------------------
__global__ void post_norm_rope(float* __restrict__ buf, const float* __restrict__ gain,
                               int nheads) {
    int head = blockIdx.x;
    int h    = head % nheads;
    int tok  = head / nheads;
    int t    = tok % TT;
    int lane = threadIdx.x;
    float* base = buf + (size_t)head * HD;
    float x0 = base[lane], x1 = base[lane + 32];
    float ss = x0*x0 + x1*x1;
#pragma unroll
    for (int off = 16; off; off >>= 1) ss += __shfl_xor_sync(0xffffffffu, ss, off);
    float rn = rsqrtf(ss * (1.0f/HD) + 1.1920929e-07f);
    x0 *= rn; x1 *= rn;
    float xp = __shfl_xor_sync(0xffffffffu, x0, 8);
    if (lane < 16) {
        int j = lane & 7;
        float inv = powf(10000.0f, -(float)(2*j) * (1.0f/16.0f));
        float ang = (float)t * inv;
        float s, c;
        sincosf(ang, &s, &c);
        x0 = (lane < 8) ? (x0*c + xp*s) : (xp*s - x0*c);
    }
    float gg = gain ? gain[h] : 1.0f;
    base[lane]      = x0 * gg;
    base[lane + 32] = x1 * gg;
}

// ---------------------------------------------------------------------------
// Flash attention v3b: 128x128 tiles, QK 8x8 / PV 8x4 microtile, 256 thr, fp32.
// PV loop c-blocked by 4 with float4 P/V loads.
// ---------------------------------------------------------------------------
__global__ __launch_bounds__(256, 1) void flash3() {
    extern __shared__ __align__(16) float fsm[];
    float (*Qs)[132] = (float(*)[132])fsm;            // [d][row]   64x132
    float (*Ks)[132] = (float(*)[132])(fsm + 8448);   // [d][col]   64x132
    float (*Vs)[68]  = (float(*)[68]) (fsm + 16896);  // [col][d]  128x68
    float (*Ps)[132] = (float(*)[132])(fsm + 25600);  // [row][col]128x132

    int qt = blockIdx.x, h = blockIdx.y, b = blockIdx.z;
    int hkv = h / GQ;
    int tid = threadIdx.x;
    int tx = tid & 15, ty = tid >> 4;
    int q0 = qt << 7;

    for (int u = tid; u < 2048; u += 256) {
        int row = u >> 4, d4 = (u & 15) << 2;
        float4 v = *(const float4*)(g_q + ((size_t)((b*TT + q0 + row)*NH + h))*HD + d4);
        Qs[d4+0][row]=v.x; Qs[d4+1][row]=v.y; Qs[d4+2][row]=v.z; Qs[d4+3][row]=v.w;
    }

    float m[8], l[8], O[8][4];
#pragma unroll
    for (int i = 0; i < 8; i++) {
        m[i] = -1e30f; l[i] = 0.f;
#pragma unroll
        for (int j = 0; j < 4; j++) O[i][j] = 0.f;
    }

    for (int kt = 0; kt <= qt; kt++) {
        __syncthreads();
        for (int u = tid; u < 2048; u += 256) {
            int row = u >> 4, d4 = (u & 15) << 2;
            size_t base = ((size_t)((b*TT + (kt<<7) + row)*NKV + hkv))*HD + d4;
            float4 kv = *(const float4*)(g_k + base);
            Ks[d4+0][row]=kv.x; Ks[d4+1][row]=kv.y; Ks[d4+2][row]=kv.z; Ks[d4+3][row]=kv.w;
            float4 vv = *(const float4*)(g_v + base);
            *(float4*)&Vs[row][d4] = vv;
        }
        __syncthreads();

        // ---- S = Q @ K^T  (8x8 microtile) ----
        float s8[8][8];
#pragma unroll
        for (int i = 0; i < 8; i++)
#pragma unroll
            for (int j = 0; j < 8; j++) s8[i][j] = 0.f;

#pragma unroll 2
        for (int d = 0; d < 64; d++) {
            float4 qa = *(float4*)&Qs[d][ty<<3], qb = *(float4*)&Qs[d][(ty<<3)+4];
            float4 ka = *(float4*)&Ks[d][tx<<3], kb = *(float4*)&Ks[d][(tx<<3)+4];
            float qv[8] = {qa.x,qa.y,qa.z,qa.w,qb.x,qb.y,qb.z,qb.w};
            float kv[8] = {ka.x,ka.y,ka.z,ka.w,kb.x,kb.y,kb.z,kb.w};
#pragma unroll
            for (int i = 0; i < 8; i++)
#pragma unroll
                for (int j = 0; j < 8; j++) s8[i][j] += qv[i]*kv[j];
        }

        const float SC = 0.125f;
        if (kt == qt) {
#pragma unroll
            for (int i = 0; i < 8; i++)
#pragma unroll
                for (int j = 0; j < 8; j++)
                    s8[i][j] = ((tx<<3)+j <= (ty<<3)+i) ? s8[i][j]*SC : -1e30f;
        } else {
#pragma unroll
            for (int i = 0; i < 8; i++)
#pragma unroll
                for (int j = 0; j < 8; j++) s8[i][j] *= SC;
        }

        // ---- online softmax ----
#pragma unroll
        for (int i = 0; i < 8; i++) {
            float rm = s8[i][0];
#pragma unroll
            for (int j = 1; j < 8; j++) rm = fmaxf(rm, s8[i][j]);
#pragma unroll
            for (int off = 8; off; off >>= 1)
                rm = fmaxf(rm, __shfl_xor_sync(0xffffffffu, rm, off));
            float mn = fmaxf(m[i], rm);
            float corr = __expf(m[i] - mn);
            m[i] = mn;
            float sum = 0.f;
#pragma unroll
            for (int j = 0; j < 8; j++) { s8[i][j] = __expf(s8[i][j] - mn); sum += s8[i][j]; }
#pragma unroll
            for (int off = 8; off; off >>= 1)
                sum += __shfl_xor_sync(0xffffffffu, sum, off);
            l[i] = l[i]*corr + sum;
#pragma unroll
            for (int j = 0; j < 4; j++) O[i][j] *= corr;
            *(float4*)&Ps[(ty<<3)+i][tx<<3]     = make_float4(s8[i][0], s8[i][1], s8[i][2], s8[i][3]);
            *(float4*)&Ps[(ty<<3)+i][(tx<<3)+4] = make_float4(s8[i][4], s8[i][5], s8[i][6], s8[i][7]);
        }
        __syncthreads();

        // ---- O += P @ V  (c-blocked by 4; P loads broadcast, V float4) ----
#pragma unroll 2
        for (int c0 = 0; c0 < 128; c0 += 4) {
            float4 pv4[8];
#pragma unroll
            for (int i = 0; i < 8; i++) pv4[i] = *(float4*)&Ps[(ty<<3)+i][c0];
            float4 vv4[4];
#pragma unroll
            for (int cc = 0; cc < 4; cc++) vv4[cc] = *(float4*)&Vs[c0+cc][tx<<2];
#pragma unroll
            for (int i = 0; i < 8; i++) {
                float pvv[4] = {pv4[i].x, pv4[i].y, pv4[i].z, pv4[i].w};
#pragma unroll
                for (int cc = 0; cc < 4; cc++) {
                    O[i][0] += pvv[cc]*vv4[cc].x;
                    O[i][1] += pvv[cc]*vv4[cc].y;
                    O[i][2] += pvv[cc]*vv4[cc].z;
                    O[i][3] += pvv[cc]*vv4[cc].w;
                }
            }
        }
    }

#pragma unroll
    for (int i = 0; i < 8; i++) {
        float inv = 1.0f / l[i];
        int row = q0 + (ty<<3) + i;
        float* dst = g_y + ((size_t)(b*TT + row))*DD + h*HD + (tx<<2);
        float4 o4 = make_float4(O[i][0]*inv, O[i][1]*inv, O[i][2]*inv, O[i][3]*inv);
        *(float4*)dst = o4;
    }
}

// ---------------------------------------------------------------------------
extern "C" void kernel_launch(void* const* d_in, const int* in_sizes, int n_in,
                              void* d_out, int out_size) {
    const float* x     = (const float*)d_in[0];
    const float* Wq    = (const float*)d_in[1];
    const float* Wk    = (const float*)d_in[2];
    const float* Wv    = (const float*)d_in[3];
    const float* Wproj = (const float*)d_in[4];
    const float* qgain = (const float*)d_in[5];
    const float* Aq    = (const float*)d_in[6];
    const float* Bq    = (const float*)d_in[7];
    const float* Av    = (const float*)d_in[8];
    const float* Bv    = (const float*)d_in[9];
    float* out = (float*)d_out;

    float *pWq, *pWv, *pq, *pk, *pv, *py;
    cudaGetSymbolAddress((void**)&pWq, g_Wq);
    cudaGetSymbolAddress((void**)&pWv, g_Wv);
    cudaGetSymbolAddress((void**)&pq,  g_q);
    cudaGetSymbolAddress((void**)&pk,  g_k);
    cudaGetSymbolAddress((void**)&pv,  g_v);
    cudaGetSymbolAddress((void**)&py,  g_y);

    // fold LoRA into weights
    merge_w<<<(DD*DD + 255)/256, 256>>>(Wq, Aq, Bq, pWq, DD);
    merge_w<<<(KD*DD + 255)/256, 256>>>(Wv, Av, Bv, pWv, KD);

    // tf32x3 tensor-core projections (~fp32 accuracy)
    int gsm = 18432 * (int)sizeof(float);   // 73728 B
    cudaFuncSetAttribute(gemm_mma3, cudaFuncAttributeMaxDynamicSharedMemorySize, gsm);
    gemm_mma3<<<dim3(DD/128, NTOK/128), 256, gsm>>>(x, pWq, pq, NTOK, DD, DD);
    gemm_mma3<<<dim3(KD/128, NTOK/128), 256, gsm>>>(x, Wk,  pk, NTOK, KD, DD);
    gemm_mma3<<<dim3(KD/128, NTOK/128), 256, gsm>>>(x, pWv, pv, NTOK, KD, DD);

    // rmsnorm + rope (+gain for q)
    post_norm_rope<<<NTOK*NH,  32>>>(pq, qgain, NH);
    post_norm_rope<<<NTOK*NKV, 32>>>(pk, nullptr, NKV);

    // attention
    int fsmB = 42496 * (int)sizeof(float);
    cudaFuncSetAttribute(flash3, cudaFuncAttributeMaxDynamicSharedMemorySize, fsmB);
    flash3<<<dim3(TT/128, NH, BB), 256, fsmB>>>();

    // output projection
    gemm_mma3<<<dim3(DD/128, NTOK/128), 256, gsm>>>(py, Wproj, out, NTOK, DD, DD);
}

// round 14
// speedup vs baseline: 1.5552x; 1.1307x over previous
#include <cuda_runtime.h>
#include <math.h>
#include <stdint.h>

#define BB   2
#define TT   2048
#define DD   1024
#define NH   16
#define NKV  4
#define HD   64
#define KD   256
#define RANK 8
#define NTOK (BB*TT)
#define GQ   (NH/NKV)

// scratch (static device allocations — allowed)
__device__ float g_Wq[DD*DD];     // merged Wq + Bq@Aq
__device__ float g_Wv[KD*DD];     // merged Wv + Bv@Av
__device__ float g_q[NTOK*DD];
__device__ float g_k[NTOK*KD];
__device__ float g_v[NTOK*KD];
__device__ float g_y[NTOK*DD];

// ---------------- helpers ---------------------------------------------------
__device__ __forceinline__ float to_tf32(float x) {
    uint32_t u; asm("cvt.rna.tf32.f32 %0, %1;" : "=r"(u) : "f"(x));
    return __uint_as_float(u);
}
__device__ __forceinline__ uint32_t f2u(float x) { return __float_as_uint(x); }

// tf32 m16n8k8 mma.sync
__device__ __forceinline__ void mma_tf32(float& c0, float& c1, float& c2, float& c3,
                                         uint32_t a0, uint32_t a1, uint32_t a2, uint32_t a3,
                                         uint32_t b0, uint32_t b1) {
    asm volatile(
        "mma.sync.aligned.m16n8k8.row.col.f32.tf32.tf32.f32 "
        "{%0,%1,%2,%3}, {%4,%5,%6,%7}, {%8,%9}, {%0,%1,%2,%3};"
        : "+f"(c0), "+f"(c1), "+f"(c2), "+f"(c3)
        : "r"(a0), "r"(a1), "r"(a2), "r"(a3), "r"(b0), "r"(b1));
}

// ---------------------------------------------------------------------------
// W_eff[o,d] = W[o,d] + sum_r Bm[o,r]*Am[r,d]    (ALPHA = 1)
// ---------------------------------------------------------------------------
__global__ void merge_w(const float* __restrict__ W, const float* __restrict__ Am,
                        const float* __restrict__ Bm, float* __restrict__ out, int rows) {
    int idx = blockIdx.x * blockDim.x + threadIdx.x;
    if (idx >= rows * DD) return;
    int o = idx / DD, d = idx - o * DD;
    float acc = W[idx];
#pragma unroll
    for (int r = 0; r < RANK; r++) acc += Bm[o*RANK + r] * Am[r*DD + d];
    out[idx] = acc;
}

// ---------------------------------------------------------------------------
// tf32x3 split-precision tensor GEMM (proven round 11).
// ---------------------------------------------------------------------------
__global__ __launch_bounds__(256, 1)
void gemm_mma3(const float* __restrict__ A, const float* __restrict__ W,
               float* __restrict__ C, int M, int N, int K) {
    extern __shared__ __align__(16) float sgm[];
    float* sa_hi = sgm;
    float* sa_lo = sgm + 4608;
    float* sb_hi = sgm + 9216;
    float* sb_lo = sgm + 13824;

    int tid = threadIdx.x;
    int wid = tid >> 5, lane = tid & 31;
    int g = lane >> 2, tg = lane & 3;
    int wm = wid >> 2, wn = wid & 3;
    int m0 = blockIdx.y << 7, n0 = blockIdx.x << 7;

    const float* aptr = A + (size_t)m0 * K;
    const float* bptr = W + (size_t)n0 * K;

    float acc[4][4][4];
#pragma unroll
    for (int mt = 0; mt < 4; mt++)
#pragma unroll
        for (int nt = 0; nt < 4; nt++)
#pragma unroll
            for (int r = 0; r < 4; r++) acc[mt][nt][r] = 0.f;

    int nk = K >> 5;
    float4 pa[4], pb[4];
#pragma unroll
    for (int it = 0; it < 4; it++) {
        int c = it * 256 + tid, r = c >> 3, c4 = (c & 7) << 2;
        pa[it] = *(const float4*)(aptr + (size_t)r * K + c4);
        pb[it] = *(const float4*)(bptr + (size_t)r * K + c4);
    }

    for (int k0 = 0; k0 < nk; k0++) {
#pragma unroll
        for (int it = 0; it < 4; it++) {
            int c = it * 256 + tid, r = c >> 3, c4 = (c & 7) << 2;
            float av[4] = {pa[it].x, pa[it].y, pa[it].z, pa[it].w};
            float bv[4] = {pb[it].x, pb[it].y, pb[it].z, pb[it].w};
            int off = r * 36 + c4;
#pragma unroll
            for (int e = 0; e < 4; e++) {
                float ah = to_tf32(av[e]);
                sa_hi[off + e] = ah;
                sa_lo[off + e] = to_tf32(av[e] - ah);
                float bh = to_tf32(bv[e]);
                sb_hi[off + e] = bh;
                sb_lo[off + e] = to_tf32(bv[e] - bh);
            }
        }
        __syncthreads();
        if (k0 + 1 < nk) {
            int koff = (k0 + 1) * 32;
#pragma unroll
            for (int it = 0; it < 4; it++) {
                int c = it * 256 + tid, r = c >> 3, c4 = (c & 7) << 2;
                pa[it] = *(const float4*)(aptr + (size_t)r * K + koff + c4);
                pb[it] = *(const float4*)(bptr + (size_t)r * K + koff + c4);
            }
        }
#pragma unroll
        for (int kk = 0; kk < 4; kk++) {
            uint32_t ah[4][4], al[4][4], bh[4][2], bl[4][2];
#pragma unroll
            for (int mt = 0; mt < 4; mt++) {
                int off = (wm * 64 + mt * 16 + g) * 36 + kk * 8 + tg;
                ah[mt][0] = f2u(sa_hi[off]);
                ah[mt][1] = f2u(sa_hi[off + 8 * 36]);
                ah[mt][2] = f2u(sa_hi[off + 4]);
                ah[mt][3] = f2u(sa_hi[off + 8 * 36 + 4]);
                al[mt][0] = f2u(sa_lo[off]);
                al[mt][1] = f2u(sa_lo[off + 8 * 36]);
                al[mt][2] = f2u(sa_lo[off + 4]);
                al[mt][3] = f2u(sa_lo[off + 8 * 36 + 4]);
            }
#pragma unroll
            for (int nt = 0; nt < 4; nt++) {
                int off = (wn * 32 + nt * 8 + g) * 36 + kk * 8 + tg;
                bh[nt][0] = f2u(sb_hi[off]);
                bh[nt][1] = f2u(sb_hi[off + 4]);
                bl[nt][0] = f2u(sb_lo[off]);
                bl[nt][1] = f2u(sb_lo[off + 4]);
            }
#pragma unroll
            for (int mt = 0; mt < 4; mt++)
#pragma unroll
                for (int nt = 0; nt < 4; nt++) {
                    mma_tf32(acc[mt][nt][0], acc[mt][nt][1], acc[mt][nt][2], acc[mt][nt][3],
                             al[mt][0], al[mt][1], al[mt][2], al[mt][3],
                             bh[nt][0], bh[nt][1]);
                    mma_tf32(acc[mt][nt][0], acc[mt][nt][1], acc[mt][nt][2], acc[mt][nt][3],
                             ah[mt][0], ah[mt][1], ah[mt][2], ah[mt][3],
                             bl[nt][0], bl[nt][1]);
                    mma_tf32(acc[mt][nt][0], acc[mt][nt][1], acc[mt][nt][2], acc[mt][nt][3],
                             ah[mt][0], ah[mt][1], ah[mt][2], ah[mt][3],
                             bh[nt][0], bh[nt][1]);
                }
        }
        __syncthreads();
    }

#pragma unroll
    for (int mt = 0; mt < 4; mt++) {
        int row = m0 + wm * 64 + mt * 16 + g;
#pragma unroll
        for (int nt = 0; nt < 4; nt++) {
            int col = n0 + wn * 32 + nt * 8 + tg * 2;
            *(float2*)(C + (size_t)row * N + col)       = make_float2(acc[mt][nt][0], acc[mt][nt][1]);
            *(float2*)(C + (size_t)(row + 8) * N + col) = make_float2(acc[mt][nt][2], acc[mt][nt][3]);
        }
    }
}

// ---------------------------------------------------------------------------
// Per-head RMSNorm + partial RoPE (pd=16) + optional gain. One warp per head.
// ---------------------------------------------------------------------------
__global__ void post_norm_rope(float* __restrict__ buf, const float* __restrict__ gain,
                               int nheads) {
    int head = blockIdx.x;
    int h    = head % nheads;
    int tok  = head / nheads;
    int t    = tok % TT;
    int lane = threadIdx.x;
    float* base = buf + (size_t)head * HD;
    float x0 = base[lane], x1 = base[lane + 32];
    float ss = x0*x0 + x1*x1;
#pragma unroll
    for (int off = 16; off; off >>= 1) ss += __shfl_xor_sync(0xffffffffu, ss, off);
    float rn = rsqrtf(ss * (1.0f/HD) + 1.1920929e-07f);
    x0 *= rn; x1 *= rn;
    float xp = __shfl_xor_sync(0xffffffffu, x0, 8);
    if (lane < 16) {
        int j = lane & 7;
        float inv = powf(10000.0f, -(float)(2*j) * (1.0f/16.0f));
        float ang = (float)t * inv;
        float s, c;
        sincosf(ang, &s, &c);
        x0 = (lane < 8) ? (x0*c + xp*s) : (xp*s - x0*c);
    }
    float gg = gain ? gain[h] : 1.0f;
    base[lane]      = x0 * gg;
    base[lane + 32] = x1 * gg;
}

// ---------------------------------------------------------------------------
// flash4: tensor-core flash attention (m16n8k8 tf32).
// CTA: 128 q-rows, 8 warps x 16 rows. K/V tiles of 64 cols.
// S = QK^T in tf32x3 (Q,K hi/lo split). P*V in tf32x2 (V split, P rna once;
// l accumulated from rounded P so the ratio error cancels).
// smem: Khl[64][136] (hi/lo interleaved), Vhl[64][136], Ps[128][68].
// ---------------------------------------------------------------------------
__global__ __launch_bounds__(256, 1) void flash4() {
    extern __shared__ __align__(16) float fsm[];
    float* Khl = fsm;              // 8704 floats
    float* Vhl = fsm + 8704;       // 8704
    float* Ps  = fsm + 17408;      // 8704 (128 x 68)

    int qt = (TT/128 - 1) - blockIdx.x;      // heavy tiles first
    int h = blockIdx.y, b = blockIdx.z;
    int hkv = h / GQ;
    int tid = threadIdx.x;
    int w = tid >> 5, lane = tid & 31;
    int g = lane >> 2, tg = lane & 3;
    int q0 = qt << 7;
    int rw = q0 + w * 16;                    // warp row base

    // Q fragments, tf32 hi/lo, rows rw+g / rw+g+8
    float qh[8][4], ql[8][4];
    {
        const float* qb = g_q + ((size_t)(b*TT + rw) * NH + h) * HD;
#pragma unroll
        for (int kk = 0; kk < 8; kk++) {
            int d = kk * 8 + tg;
            float v0 = qb[(size_t)g * DD + d];
            float v1 = qb[(size_t)(g + 8) * DD + d];
            float v2 = qb[(size_t)g * DD + d + 4];
            float v3 = qb[(size_t)(g + 8) * DD + d + 4];
            qh[kk][0] = to_tf32(v0); ql[kk][0] = to_tf32(v0 - qh[kk][0]);
            qh[kk][1] = to_tf32(v1); ql[kk][1] = to_tf32(v1 - qh[kk][1]);
            qh[kk][2] = to_tf32(v2); ql[kk][2] = to_tf32(v2 - qh[kk][2]);
            qh[kk][3] = to_tf32(v3); ql[kk][3] = to_tf32(v3 - qh[kk][3]);
        }
    }

    float m0 = -1e30f, m1 = -1e30f, l0 = 0.f, l1 = 0.f;
    float o[8][4];
#pragma unroll
    for (int nt = 0; nt < 8; nt++)
#pragma unroll
        for (int r = 0; r < 4; r++) o[nt][r] = 0.f;

    int nkt = 2 * qt + 2;
    for (int kt = 0; kt < nkt; kt++) {
        __syncthreads();
        // cooperative K/V tile load + hi/lo split (64 rows x 64 d)
        {
            int c = tid >> 2, d0 = (tid & 3) << 4;
            size_t src = ((size_t)((b*TT + (kt << 6) + c) * NKV + hkv)) * HD + d0;
            float* kr = Khl + c * 136 + 2 * d0;
            float* vr = Vhl + c * 136 + 2 * d0;
#pragma unroll
            for (int i = 0; i < 4; i++) {
                float4 kv = *(const float4*)(g_k + src + i * 4);
                float a0 = to_tf32(kv.x), a1 = to_tf32(kv.y), a2 = to_tf32(kv.z), a3 = to_tf32(kv.w);
                *(float4*)(kr + i*8)     = make_float4(a0, to_tf32(kv.x - a0), a1, to_tf32(kv.y - a1));
                *(float4*)(kr + i*8 + 4) = make_float4(a2, to_tf32(kv.z - a2), a3, to_tf32(kv.w - a3));
                float4 vv = *(const float4*)(g_v + src + i * 4);
                float b0 = to_tf32(vv.x), b1 = to_tf32(vv.y), b2 = to_tf32(vv.z), b3 = to_tf32(vv.w);
                *(float4*)(vr + i*8)     = make_float4(b0, to_tf32(vv.x - b0), b1, to_tf32(vv.y - b1));
                *(float4*)(vr + i*8 + 4) = make_float4(b2, to_tf32(vv.z - b2), b3, to_tf32(vv.w - b3));
            }
        }
        __syncthreads();

        // ---- S = Q K^T (tf32x3) ----
        float s[8][4];
#pragma unroll
        for (int nt = 0; nt < 8; nt++)
#pragma unroll
            for (int r = 0; r < 4; r++) s[nt][r] = 0.f;

#pragma unroll
        for (int kk = 0; kk < 8; kk++) {
#pragma unroll
            for (int nt = 0; nt < 8; nt++) {
                const float* kp = Khl + (nt * 8 + g) * 136 + 2 * (kk * 8 + tg);
                float2 p0 = *(const float2*)kp;        // (hi, lo) at k=tg
                float2 p1 = *(const float2*)(kp + 8);  // (hi, lo) at k=tg+4
                mma_tf32(s[nt][0], s[nt][1], s[nt][2], s[nt][3],
                         f2u(ql[kk][0]), f2u(ql[kk][1]), f2u(ql[kk][2]), f2u(ql[kk][3]),
                         f2u(p0.x), f2u(p1.x));
                mma_tf32(s[nt][0], s[nt][1], s[nt][2], s[nt][3],
                         f2u(qh[kk][0]), f2u(qh[kk][1]), f2u(qh[kk][2]), f2u(qh[kk][3]),
                         f2u(p0.y), f2u(p1.y));
                mma_tf32(s[nt][0], s[nt][1], s[nt][2], s[nt][3],
                         f2u(qh[kk][0]), f2u(qh[kk][1]), f2u(qh[kk][2]), f2u(qh[kk][3]),
                         f2u(p0.x), f2u(p1.x));
            }
        }

        // ---- scale + causal mask ----
        const float SC = 0.125f;
        if (kt >= 2 * qt) {
            int cb = kt << 6;
            int r0 = rw + g, r1 = rw + g + 8;
#pragma unroll
            for (int nt = 0; nt < 8; nt++) {
                int col = cb + nt * 8 + 2 * tg;
                s[nt][0] = (col     <= r0) ? s[nt][0] * SC : -1e30f;
                s[nt][1] = (col + 1 <= r0) ? s[nt][1] * SC : -1e30f;
                s[nt][2] = (col     <= r1) ? s[nt][2] * SC : -1e30f;
                s[nt][3] = (col + 1 <= r1) ? s[nt][3] * SC : -1e30f;
            }
        } else {
#pragma unroll
            for (int nt = 0; nt < 8; nt++)
#pragma unroll
                for (int r = 0; r < 4; r++) s[nt][r] *= SC;
        }

        // ---- online softmax (rows g, g+8; 4 lanes per row => shfl 1,2) ----
        float mx0 = s[0][0], mx1 = s[0][2];
#pragma unroll
        for (int nt = 0; nt < 8; nt++) {
            mx0 = fmaxf(mx0, fmaxf(s[nt][0], s[nt][1]));
            mx1 = fmaxf(mx1, fmaxf(s[nt][2], s[nt][3]));
        }
        mx0 = fmaxf(mx0, __shfl_xor_sync(0xffffffffu, mx0, 1));
        mx0 = fmaxf(mx0, __shfl_xor_sync(0xffffffffu, mx0, 2));
        mx1 = fmaxf(mx1, __shfl_xor_sync(0xffffffffu, mx1, 1));
        mx1 = fmaxf(mx1, __shfl_xor_sync(0xffffffffu, mx1, 2));
        float mn0 = fmaxf(m0, mx0), mn1 = fmaxf(m1, mx1);
        float cr0 = __expf(m0 - mn0), cr1 = __expf(m1 - mn1);
        m0 = mn0; m1 = mn1;
        float su0 = 0.f, su1 = 0.f;
#pragma unroll
        for (int nt = 0; nt < 8; nt++) {
            float p;
            p = to_tf32(__expf(s[nt][0] - mn0)); s[nt][0] = p; su0 += p;
            p = to_tf32(__expf(s[nt][1] - mn0)); s[nt][1] = p; su0 += p;
            p = to_tf32(__expf(s[nt][2] - mn1)); s[nt][2] = p; su1 += p;
            p = to_tf32(__expf(s[nt][3] - mn1)); s[nt][3] = p; su1 += p;
        }
        su0 += __shfl_xor_sync(0xffffffffu, su0, 1);
        su0 += __shfl_xor_sync(0xffffffffu, su0, 2);
        su1 += __shfl_xor_sync(0xffffffffu, su1, 1);
        su1 += __shfl_xor_sync(0xffffffffu, su1, 2);
        l0 = l0 * cr0 + su0;
        l1 = l1 * cr1 + su1;

        // correct O, stage P (warp-private rows => __syncwarp only)
#pragma unroll
        for (int nt = 0; nt < 8; nt++) {
            o[nt][0] *= cr0; o[nt][1] *= cr0; o[nt][2] *= cr1; o[nt][3] *= cr1;
            *(float2*)(Ps + (w*16 + g) * 68 + nt * 8 + 2 * tg)     = make_float2(s[nt][0], s[nt][1]);
            *(float2*)(Ps + (w*16 + g + 8) * 68 + nt * 8 + 2 * tg) = make_float2(s[nt][2], s[nt][3]);
        }
        __syncwarp();

        // ---- O += P V (tf32x2: V hi/lo) ----
#pragma unroll
        for (int kk = 0; kk < 8; kk++) {
            const float* pp = Ps + (w*16 + g) * 68 + kk * 8 + tg;
            uint32_t a0 = f2u(pp[0]), a1 = f2u(pp[8 * 68]), a2 = f2u(pp[4]), a3 = f2u(pp[8 * 68 + 4]);
#pragma unroll
            for (int nt = 0; nt < 8; nt++) {
                const float* vp = Vhl + (kk * 8 + tg) * 136 + 2 * (nt * 8 + g);
                float2 v0 = *(const float2*)vp;              // (hi,lo) at k=col tg
                float2 v1 = *(const float2*)(vp + 4 * 136);  // (hi,lo) at k=col tg+4
                mma_tf32(o[nt][0], o[nt][1], o[nt][2], o[nt][3],
                         a0, a1, a2, a3, f2u(v0.x), f2u(v1.x));
                mma_tf32(o[nt][0], o[nt][1], o[nt][2], o[nt][3],
                         a0, a1, a2, a3, f2u(v0.y), f2u(v1.y));
            }
        }
    }

    // ---- normalize + store ----
    float i0 = 1.0f / l0, i1 = 1.0f / l1;
#pragma unroll
    for (int nt = 0; nt < 8; nt++) {
        size_t r0 = (size_t)(b*TT + rw + g) * DD + h * HD + nt * 8 + 2 * tg;
        size_t r1 = (size_t)(b*TT + rw + g + 8) * DD + h * HD + nt * 8 + 2 * tg;
        *(float2*)(g_y + r0) = make_float2(o[nt][0] * i0, o[nt][1] * i0);
        *(float2*)(g_y + r1) = make_float2(o[nt][2] * i1, o[nt][3] * i1);
    }
}

// ---------------------------------------------------------------------------
extern "C" void kernel_launch(void* const* d_in, const int* in_sizes, int n_in,
                              void* d_out, int out_size) {
    const float* x     = (const float*)d_in[0];
    const float* Wq    = (const float*)d_in[1];
    const float* Wk    = (const float*)d_in[2];
    const float* Wv    = (const float*)d_in[3];
    const float* Wproj = (const float*)d_in[4];
    const float* qgain = (const float*)d_in[5];
    const float* Aq    = (const float*)d_in[6];
    const float* Bq    = (const float*)d_in[7];
    const float* Av    = (const float*)d_in[8];
    const float* Bv    = (const float*)d_in[9];
    float* out = (float*)d_out;

    float *pWq, *pWv, *pq, *pk, *pv, *py;
    cudaGetSymbolAddress((void**)&pWq, g_Wq);
    cudaGetSymbolAddress((void**)&pWv, g_Wv);
    cudaGetSymbolAddress((void**)&pq,  g_q);
    cudaGetSymbolAddress((void**)&pk,  g_k);
    cudaGetSymbolAddress((void**)&pv,  g_v);
    cudaGetSymbolAddress((void**)&py,  g_y);

    // fold LoRA into weights
    merge_w<<<(DD*DD + 255)/256, 256>>>(Wq, Aq, Bq, pWq, DD);
    merge_w<<<(KD*DD + 255)/256, 256>>>(Wv, Av, Bv, pWv, KD);

    // tf32x3 tensor-core projections
    int gsm = 18432 * (int)sizeof(float);
    cudaFuncSetAttribute(gemm_mma3, cudaFuncAttributeMaxDynamicSharedMemorySize, gsm);
    gemm_mma3<<<dim3(DD/128, NTOK/128), 256, gsm>>>(x, pWq, pq, NTOK, DD, DD);
    gemm_mma3<<<dim3(KD/128, NTOK/128), 256, gsm>>>(x, Wk,  pk, NTOK, KD, DD);
    gemm_mma3<<<dim3(KD/128, NTOK/128), 256, gsm>>>(x, pWv, pv, NTOK, KD, DD);

    // rmsnorm + rope (+gain for q)
    post_norm_rope<<<NTOK*NH,  32>>>(pq, qgain, NH);
    post_norm_rope<<<NTOK*NKV, 32>>>(pk, nullptr, NKV);

    // tensor-core flash attention
    int fsm4 = 26112 * (int)sizeof(float);   // 104448 B
    cudaFuncSetAttribute(flash4, cudaFuncAttributeMaxDynamicSharedMemorySize, fsm4);
    flash4<<<dim3(TT/128, NH, BB), 256, fsm4>>>();

    // output projection
    gemm_mma3<<<dim3(DD/128, NTOK/128), 256, gsm>>>(py, Wproj, out, NTOK, DD, DD);
}